// round 16
// baseline (speedup 1.0000x reference)
#include <cuda_runtime.h>
#include <cuda_bf16.h>
#include <cuda_fp16.h>
#include <math.h>
#include <stdint.h>

#define IN_DIM 256
#define OUT_DIM 256
#define DK 32
#define MAXN 50000
#define MAXE 800000

// ---------------- static device scratch (no cudaMalloc anywhere) ------------
__device__ __half g_TE [MAXN * IN_DIM];        // concat(user,item) fp16
__device__ __half g_X  [MAXN * IN_DIM];        // x fp16
__device__ __half g_AG [MAXN * OUT_DIM];       // attention output fp16
__device__ __half g_W  [4 * OUT_DIM * IN_DIM]; // Wq,Wk,Wv,Wo fp16
__device__ __half g_Qh [MAXN * OUT_DIM];
__device__ __half g_Kh [MAXN * OUT_DIM];       // K + rel, dense
__device__ __half g_Vh [MAXN * OUT_DIM];       // V, dense
__device__ int   g_deg[MAXN];
__device__ int   g_ptr[MAXN + 1];
__device__ int   g_cur[MAXN];
__device__ int   g_src[MAXE];
__device__ unsigned long long g_scanstate[64]; // decoupled-lookback state

// ---------------- asm helpers (family-common: sm_80+) -------------------------
__device__ __forceinline__ uint32_t smem_u32(const void* p) {
    uint32_t a;
    asm("{ .reg .u64 t; cvta.to.shared.u64 t, %1; cvt.u32.u64 %0, t; }"
        : "=r"(a) : "l"(p));
    return a;
}
__device__ __forceinline__ void cp16(uint32_t dst, const void* src, uint32_t bytes) {
    asm volatile("cp.async.cg.shared.global [%0], [%1], 16, %2;"
                 :: "r"(dst), "l"(src), "r"(bytes));
}
#define CP_COMMIT() asm volatile("cp.async.commit_group;" ::: "memory")
#define CP_WAIT(n)  asm volatile("cp.async.wait_group %0;" :: "n"(n) : "memory")

__device__ __forceinline__ void ldm_x4(uint32_t* r, uint32_t addr) {
    asm volatile("ldmatrix.sync.aligned.m8n8.x4.shared.b16 {%0,%1,%2,%3}, [%4];"
                 : "=r"(r[0]), "=r"(r[1]), "=r"(r[2]), "=r"(r[3]) : "r"(addr));
}
__device__ __forceinline__ void ldm_x2(uint32_t* r, uint32_t addr) {
    asm volatile("ldmatrix.sync.aligned.m8n8.x2.shared.b16 {%0,%1}, [%2];"
                 : "=r"(r[0]), "=r"(r[1]) : "r"(addr));
}
__device__ __forceinline__ void mma_f16(float* c, const uint32_t* a, const uint32_t* b) {
    asm volatile("mma.sync.aligned.m16n8k16.row.col.f32.f16.f16.f32 "
                 "{%0,%1,%2,%3}, {%4,%5,%6,%7}, {%8,%9}, {%0,%1,%2,%3};"
                 : "+f"(c[0]), "+f"(c[1]), "+f"(c[2]), "+f"(c[3])
                 : "r"(a[0]), "r"(a[1]), "r"(a[2]), "r"(a[3]), "r"(b[0]), "r"(b[1]));
}

// ---------------- merged prep: TE + x + W conversions AND degree count --------
__global__ void prep_kernel(const float4* __restrict__ user,
                            const float4* __restrict__ item,
                            const float4* __restrict__ x,
                            const float4* __restrict__ W0,
                            const float4* __restrict__ W1,
                            const float4* __restrict__ W2,
                            const float4* __restrict__ W3,
                            const int4* __restrict__ col4, int E4, int E,
                            const int* __restrict__ col,
                            int nu4, int total4) {
    __half2* te = reinterpret_cast<__half2*>(g_TE);
    __half2* xx = reinterpret_cast<__half2*>(g_X);
    __half2* ww = reinterpret_cast<__half2*>(g_W);
    const float4* Ws[4] = {W0, W1, W2, W3};
    const int tot_ax  = total4 * 2;
    const int tot_w   = tot_ax + 65536;
    const int tot_all = tot_w + E4;
    int gid = blockIdx.x * blockDim.x + threadIdx.x;
    for (int i = gid; i < tot_all; i += gridDim.x * blockDim.x) {
        if (i < total4) {
            float4 v = (i < nu4) ? user[i] : item[i - nu4];
            te[2 * i]     = __floats2half2_rn(v.x, v.y);
            te[2 * i + 1] = __floats2half2_rn(v.z, v.w);
        } else if (i < tot_ax) {
            int j = i - total4;
            float4 v = x[j];
            xx[2 * j]     = __floats2half2_rn(v.x, v.y);
            xx[2 * j + 1] = __floats2half2_rn(v.z, v.w);
        } else if (i < tot_w) {
            int j = i - tot_ax;
            float4 v = Ws[j >> 14][j & 16383];
            ww[2 * j]     = __floats2half2_rn(v.x, v.y);
            ww[2 * j + 1] = __floats2half2_rn(v.z, v.w);
        } else {
            int4 c = col4[i - tot_w];
            atomicAdd(&g_deg[c.x], 1);
            atomicAdd(&g_deg[c.y], 1);
            atomicAdd(&g_deg[c.z], 1);
            atomicAdd(&g_deg[c.w], 1);
        }
    }
    if (gid == 0)
        for (int e = E4 * 4; e < E; e++) atomicAdd(&g_deg[col[e]], 1);
}

// ---------------- single-pass decoupled-lookback scan -------------------------
// grid = ceil(n/1024) (<=49 blocks, all resident), block = 1024.
// g_scanstate[b] = (flag<<32) | sum; flag: 0=invalid, 1=partial, 2=inclusive.
__global__ void scan_kernel(int n, int E) {
    __shared__ int sh[1024];
    __shared__ int s_base;
    const int b = blockIdx.x;
    const int tid = threadIdx.x;
    const int i = b * 1024 + tid;
    int v = (i < n) ? g_deg[i] : 0;
    sh[tid] = v;
    __syncthreads();
    for (int off = 1; off < 1024; off <<= 1) {
        int t = (tid >= off) ? sh[tid - off] : 0;
        __syncthreads();
        sh[tid] += t;
        __syncthreads();
    }
    if (tid == 0) {
        unsigned long long total = (unsigned long long)(unsigned)sh[1023];
        atomicExch(&g_scanstate[b], (1ull << 32) | total);
        int base = 0;
        for (int j = b - 1; j >= 0;) {
            unsigned long long st;
            do { st = atomicAdd(&g_scanstate[j], 0ull); } while ((st >> 32) == 0ull);
            base += (int)(unsigned)st;
            if ((st >> 32) == 2ull) break;
            j--;
        }
        atomicExch(&g_scanstate[b], (2ull << 32) |
                   (unsigned long long)(unsigned)(base + sh[1023]));
        s_base = base;
    }
    __syncthreads();
    if (i < n) {
        int p = s_base + sh[tid] - v;
        g_ptr[i] = p;
        g_cur[i] = p;
    }
    if (i == 0) g_ptr[n] = E;
}

__global__ void scatter_kernel(const int4* __restrict__ row4,
                               const int4* __restrict__ col4, int E4, int E,
                               const int* __restrict__ row,
                               const int* __restrict__ col) {
    int i = blockIdx.x * blockDim.x + threadIdx.x;
    for (int e = i; e < E4; e += gridDim.x * blockDim.x) {
        int4 r = row4[e];
        int4 c = col4[e];
        g_src[atomicAdd(&g_cur[c.x], 1)] = r.x;
        g_src[atomicAdd(&g_cur[c.y], 1)] = r.y;
        g_src[atomicAdd(&g_cur[c.z], 1)] = r.z;
        g_src[atomicAdd(&g_cur[c.w], 1)] = r.w;
    }
    if (i == 0)
        for (int e = E4 * 4; e < E; e++)
            g_src[atomicAdd(&g_cur[col[e]], 1)] = row[e];
}

// ---------------- fused QKV fp16 HMMA GEMM (grid.z selects projection) --------
#define S_A  0
#define S_W  16384
#define STG  32768
#define GEMM_SMEM (2 * STG)

__device__ __forceinline__ void gemm_core(
    const __half* __restrict__ A, const __half* __restrict__ W,
    const float* __restrict__ bias, const float* __restrict__ bias2,
    float* __restrict__ C, __half* __restrict__ Ch, int M,
    char* smem, uint32_t sb) {
    const int tid = threadIdx.x, wid = tid >> 5, lid = tid & 31;
    const int bm = blockIdx.x * 128;
    const int bn = blockIdx.y * 128;
    const int wm = (wid >> 2) * 64;
    const int wn = (wid & 3) * 32;

    float acc[4][4][4];
#pragma unroll
    for (int i = 0; i < 4; i++)
#pragma unroll
        for (int j = 0; j < 4; j++)
#pragma unroll
            for (int k = 0; k < 4; k++) acc[i][j][k] = 0.f;

    auto load_tile = [&](int kt, int stage) {
        const int koff = kt * 64;
        const uint32_t base = sb + stage * STG;
#pragma unroll
        for (int i = tid; i < 1024; i += 256) {
            int r = i >> 3, c = i & 7;
            int grow = bm + r;
            const char* g = (const char*)A + (size_t)grow * 512 + koff * 2 + c * 16;
            uint32_t d = base + S_A + r * 128 + ((c ^ (r & 7)) << 4);
            cp16(d, g, (grow < M) ? 16u : 0u);
        }
#pragma unroll
        for (int i = tid; i < 1024; i += 256) {
            int r = i >> 3, c = i & 7;
            const char* g = (const char*)W + (size_t)(bn + r) * 512 + koff * 2 + c * 16;
            uint32_t d = base + S_W + r * 128 + ((c ^ (r & 7)) << 4);
            cp16(d, g, 16u);
        }
        CP_COMMIT();
    };

    load_tile(0, 0);

#pragma unroll
    for (int t = 0; t < 4; t++) {
        const int st = t & 1;
        if (t + 1 < 4) {
            load_tile(t + 1, (t + 1) & 1);
            CP_WAIT(1);
        } else {
            CP_WAIT(0);
        }
        __syncthreads();

        const uint32_t base = sb + st * STG;
#pragma unroll
        for (int ks = 0; ks < 4; ks++) {
            uint32_t a[4][4], b[4][2];
#pragma unroll
            for (int ma = 0; ma < 4; ma++) {
                int ar = wm + ma * 16 + (lid & 15);
                int ch = ks * 2 + (lid >> 4);
                ldm_x4(a[ma], base + S_A + ar * 128 + ((ch ^ (ar & 7)) << 4));
            }
#pragma unroll
            for (int na = 0; na < 4; na++) {
                int nr = wn + na * 8 + (lid & 7);
                int ch = ks * 2 + ((lid >> 3) & 1);
                ldm_x2(b[na], base + S_W + nr * 128 + ((ch ^ (nr & 7)) << 4));
            }
#pragma unroll
            for (int ma = 0; ma < 4; ma++)
#pragma unroll
                for (int na = 0; na < 4; na++)
                    mma_f16(acc[ma][na], a[ma], b[na]);
        }
        __syncthreads();
    }

    const int g = lid >> 2;
    const int tg = (lid & 3) * 2;
#pragma unroll
    for (int ma = 0; ma < 4; ma++) {
        int mr = bm + wm + ma * 16 + g;
#pragma unroll
        for (int na = 0; na < 4; na++) {
            int nc = bn + wn + na * 8 + tg;
            float b0 = bias[nc], b1 = bias[nc + 1];
            if (bias2) { b0 += bias2[nc]; b1 += bias2[nc + 1]; }
            float o00 = acc[ma][na][0] + b0, o01 = acc[ma][na][1] + b1;
            float o10 = acc[ma][na][2] + b0, o11 = acc[ma][na][3] + b1;
            if (Ch) {
                if (mr < M)
                    *(__half2*)(Ch + (size_t)mr * OUT_DIM + nc) = __floats2half2_rn(o00, o01);
                if (mr + 8 < M)
                    *(__half2*)(Ch + (size_t)(mr + 8) * OUT_DIM + nc) = __floats2half2_rn(o10, o11);
            } else {
                if (mr < M)
                    *(float2*)(C + (size_t)mr * OUT_DIM + nc) = make_float2(o00, o01);
                if (mr + 8 < M)
                    *(float2*)(C + (size_t)(mr + 8) * OUT_DIM + nc) = make_float2(o10, o11);
            }
        }
    }
}

// grid.z: 0 -> Q = TE@Wq, 1 -> K = TE@Wk + rel, 2 -> V = X@Wv
__global__ void __launch_bounds__(256, 2)
gemm_qkv_kernel(const float* __restrict__ rel,
                const float* __restrict__ bq, const float* __restrict__ bk,
                const float* __restrict__ bv, int M) {
    extern __shared__ char smem[];
    const uint32_t sb = smem_u32(smem);
    const int z = blockIdx.z;
    const __half* A  = (z == 2) ? g_X : g_TE;
    const __half* W  = g_W + (size_t)z * 65536;
    const float* bias  = (z == 0) ? bq : (z == 1) ? bk : bv;
    const float* bias2 = (z == 1) ? rel : nullptr;
    __half* Ch = (z == 0) ? g_Qh : (z == 1) ? g_Kh : g_Vh;
    gemm_core(A, W, bias, bias2, nullptr, Ch, M, smem, sb);
}

__global__ void __launch_bounds__(256, 2)
gemm_out_kernel(const float* __restrict__ bo, float* __restrict__ out, int M) {
    extern __shared__ char smem[];
    const uint32_t sb = smem_u32(smem);
    gemm_core(g_AG, g_W + 3 * 65536, bo, nullptr, out, nullptr, M, smem, sb);
}

// ---------------- per-node attention: 64 thr/node, separate K/V, 4-edge ILP ---
__global__ void __launch_bounds__(256)
attn_kernel(int N) {
    const int n = blockIdx.x * 4 + (threadIdx.x >> 6);
    if (n >= N) return;
    const int tid = threadIdx.x & 63;
    const int w = tid >> 5, lid = tid & 31;
    const int head = w * 4 + (lid >> 3);
    const int sub = lid & 7;
    const int qidx = head * 8 + sub;

    const int beg = g_ptr[n];
    const int end = g_ptr[n + 1];

    const uint2* Q2 = reinterpret_cast<const uint2*>(g_Qh);
    const uint2* K2 = reinterpret_cast<const uint2*>(g_Kh);
    const uint2* V2 = reinterpret_cast<const uint2*>(g_Vh);
    const int* __restrict__ src = g_src;

    uint2 qr = Q2[(size_t)n * 64 + qidx];
    float2 q01 = __half22float2(*(__half2*)&qr.x);
    float2 q23 = __half22float2(*(__half2*)&qr.y);
    const float inv_sqrt_dk = 0.17677669529663689f;

    float s = 0.f;
    float a0 = 0.f, a1 = 0.f, a2 = 0.f, a3 = 0.f;

    int i = beg;
    for (; i + 3 < end; i += 4) {
        int r0 = src[i], r1 = src[i + 1], r2 = src[i + 2], r3 = src[i + 3];
        uint2 k0 = K2[(size_t)r0 * 64 + qidx];
        uint2 k1 = K2[(size_t)r1 * 64 + qidx];
        uint2 k2 = K2[(size_t)r2 * 64 + qidx];
        uint2 k3 = K2[(size_t)r3 * 64 + qidx];
        uint2 v0 = V2[(size_t)r0 * 64 + qidx];
        uint2 v1 = V2[(size_t)r1 * 64 + qidx];
        uint2 v2 = V2[(size_t)r2 * 64 + qidx];
        uint2 v3 = V2[(size_t)r3 * 64 + qidx];

        float2 kA01 = __half22float2(*(__half2*)&k0.x), kA23 = __half22float2(*(__half2*)&k0.y);
        float2 kB01 = __half22float2(*(__half2*)&k1.x), kB23 = __half22float2(*(__half2*)&k1.y);
        float2 kC01 = __half22float2(*(__half2*)&k2.x), kC23 = __half22float2(*(__half2*)&k2.y);
        float2 kD01 = __half22float2(*(__half2*)&k3.x), kD23 = __half22float2(*(__half2*)&k3.y);

        float pA = q01.x * kA01.x + q01.y * kA01.y + q23.x * kA23.x + q23.y * kA23.y;
        float pB = q01.x * kB01.x + q01.y * kB01.y + q23.x * kB23.x + q23.y * kB23.y;
        float pC = q01.x * kC01.x + q01.y * kC01.y + q23.x * kC23.x + q23.y * kC23.y;
        float pD = q01.x * kD01.x + q01.y * kD01.y + q23.x * kD23.x + q23.y * kD23.y;

        pA += __shfl_xor_sync(0xffffffffu, pA, 4);
        pB += __shfl_xor_sync(0xffffffffu, pB, 4);
        pC += __shfl_xor_sync(0xffffffffu, pC, 4);
        pD += __shfl_xor_sync(0xffffffffu, pD, 4);
        pA += __shfl_xor_sync(0xffffffffu, pA, 2);
        pB += __shfl_xor_sync(0xffffffffu, pB, 2);
        pC += __shfl_xor_sync(0xffffffffu, pC, 2);
        pD += __shfl_xor_sync(0xffffffffu, pD, 2);
        pA += __shfl_xor_sync(0xffffffffu, pA, 1);
        pB += __shfl_xor_sync(0xffffffffu, pB, 1);
        pC += __shfl_xor_sync(0xffffffffu, pC, 1);
        pD += __shfl_xor_sync(0xffffffffu, pD, 1);

        float eA = __expf(pA * inv_sqrt_dk);
        float eB = __expf(pB * inv_sqrt_dk);
        float eC = __expf(pC * inv_sqrt_dk);
        float eD = __expf(pD * inv_sqrt_dk);
        s += (eA + eB) + (eC + eD);

        float2 vA01 = __half22float2(*(__half2*)&v0.x), vA23 = __half22float2(*(__half2*)&v0.y);
        float2 vB01 = __half22float2(*(__half2*)&v1.x), vB23 = __half22float2(*(__half2*)&v1.y);
        float2 vC01 = __half22float2(*(__half2*)&v2.x), vC23 = __half22float2(*(__half2*)&v2.y);
        float2 vD01 = __half22float2(*(__half2*)&v3.x), vD23 = __half22float2(*(__half2*)&v3.y);

        a0 += eA * vA01.x + eB * vB01.x + eC * vC01.x + eD * vD01.x;
        a1 += eA * vA01.y + eB * vB01.y + eC * vC01.y + eD * vD01.y;
        a2 += eA * vA23.x + eB * vB23.x + eC * vC23.x + eD * vD23.x;
        a3 += eA * vA23.y + eB * vB23.y + eC * vC23.y + eD * vD23.y;
    }
    for (; i < end; i++) {
        int r0 = src[i];
        uint2 k0 = K2[(size_t)r0 * 64 + qidx];
        uint2 v0 = V2[(size_t)r0 * 64 + qidx];
        float2 k01 = __half22float2(*(__half2*)&k0.x), k23 = __half22float2(*(__half2*)&k0.y);
        float p = q01.x * k01.x + q01.y * k01.y + q23.x * k23.x + q23.y * k23.y;
        p += __shfl_xor_sync(0xffffffffu, p, 4);
        p += __shfl_xor_sync(0xffffffffu, p, 2);
        p += __shfl_xor_sync(0xffffffffu, p, 1);
        float e = __expf(p * inv_sqrt_dk);
        s += e;
        float2 v01 = __half22float2(*(__half2*)&v0.x), v23 = __half22float2(*(__half2*)&v0.y);
        a0 += e * v01.x;
        a1 += e * v01.y;
        a2 += e * v23.x;
        a3 += e * v23.y;
    }

    float o0 = 0.f, o1 = 0.f, o2 = 0.f, o3 = 0.f;
    if (s > 0.f) {
        float inv = 1.f / s;
        o0 = a0 * inv; o1 = a1 * inv; o2 = a2 * inv; o3 = a3 * inv;
    }
    uint2 outv;
    *(__half2*)&outv.x = __floats2half2_rn(o0, o1);
    *(__half2*)&outv.y = __floats2half2_rn(o2, o3);
    reinterpret_cast<uint2*>(g_AG)[(size_t)n * 64 + qidx] = outv;
}

// ---------------- launch --------------------------------------------------------
extern "C" void kernel_launch(void* const* d_in, const int* in_sizes, int n_in,
                              void* d_out, int out_size) {
    const float* x    = (const float*)d_in[0];
    const int*   row  = (const int*)  d_in[1];
    const int*   col  = (const int*)  d_in[2];
    const float* rel  = (const float*)d_in[3];
    const float* user = (const float*)d_in[4];
    const float* item = (const float*)d_in[5];
    const float* Wq   = (const float*)d_in[6];
    const float* bq   = (const float*)d_in[7];
    const float* Wk   = (const float*)d_in[8];
    const float* bk   = (const float*)d_in[9];
    const float* Wv   = (const float*)d_in[10];
    const float* bv   = (const float*)d_in[11];
    const float* Wo   = (const float*)d_in[12];
    const float* bo   = (const float*)d_in[13];
    float* out = (float*)d_out;

    const int N  = in_sizes[0] / IN_DIM;
    const int E  = in_sizes[1];
    const int NU = in_sizes[4] / IN_DIM;
    const int E4 = E >> 2;

    int* dDeg;
    unsigned long long* dState;
    cudaGetSymbolAddress((void**)&dDeg, g_deg);
    cudaGetSymbolAddress((void**)&dState, g_scanstate);

    cudaFuncSetAttribute(gemm_qkv_kernel,
                         cudaFuncAttributeMaxDynamicSharedMemorySize, GEMM_SMEM);
    cudaFuncSetAttribute(gemm_out_kernel,
                         cudaFuncAttributeMaxDynamicSharedMemorySize, GEMM_SMEM);

    // 0. zero degree counters + scan state (async, tiny)
    cudaMemsetAsync(dDeg, 0, (size_t)N * sizeof(int), 0);
    cudaMemsetAsync(dState, 0, 64 * sizeof(unsigned long long), 0);

    // 1. merged prep: fp16 conversions + degree count — one launch
    {
        int total4 = N * (IN_DIM / 4);
        int nu4 = NU * (IN_DIM / 4);
        prep_kernel<<<2560, 256>>>((const float4*)user, (const float4*)item,
                                   (const float4*)x,
                                   (const float4*)Wq, (const float4*)Wk,
                                   (const float4*)Wv, (const float4*)Wo,
                                   (const int4*)col, E4, E, col,
                                   nu4, total4);
    }

    // 2. single-pass decoupled-lookback scan -> g_ptr, g_cur
    int nb = (N + 1023) / 1024;
    scan_kernel<<<nb, 1024>>>(N, E);
    scatter_kernel<<<(E4 + 255) / 256, 256>>>((const int4*)row, (const int4*)col,
                                              E4, E, row, col);

    // 3. fused Q/K/V projections — ONE launch, grid.z = 3
    dim3 gg((N + 127) / 128, 2, 3);
    gemm_qkv_kernel<<<gg, 256, GEMM_SMEM>>>(rel, bq, bk, bv, N);

    // 4. attention (R13 4-edge ILP version)
    attn_kernel<<<(N + 3) / 4, 256>>>(N);

    // 5. output projection -> fp32 out
    dim3 go((N + 127) / 128, 2);
    gemm_out_kernel<<<go, 256, GEMM_SMEM>>>(bo, out, N);
}

// round 17
// speedup vs baseline: 1.0083x; 1.0083x over previous
#include <cuda_runtime.h>
#include <cuda_bf16.h>
#include <cuda_fp16.h>
#include <math.h>
#include <stdint.h>

#define IN_DIM 256
#define OUT_DIM 256
#define DK 32
#define MAXN 50000
#define MAXE 800000

// ---------------- static device scratch (no cudaMalloc anywhere) ------------
__device__ __half g_TE [MAXN * IN_DIM];        // concat(user,item) fp16
__device__ __half g_X  [MAXN * IN_DIM];        // x fp16
__device__ __half g_AG [MAXN * OUT_DIM];       // attention output fp16
__device__ __half g_W  [4 * OUT_DIM * IN_DIM]; // Wq,Wk,Wv,Wo fp16
__device__ __half g_Qh [MAXN * OUT_DIM];
__device__ __half g_Kh [MAXN * OUT_DIM];       // K + rel, dense
__device__ __half g_Vh [MAXN * OUT_DIM];       // V, dense
__device__ int   g_deg[MAXN];
__device__ int   g_ptr[MAXN + 1];
__device__ int   g_cur[MAXN];
__device__ int   g_src[MAXE];
__device__ unsigned long long g_scanstate[64];

// ---------------- asm helpers (family-common: sm_80+) -------------------------
__device__ __forceinline__ uint32_t smem_u32(const void* p) {
    uint32_t a;
    asm("{ .reg .u64 t; cvta.to.shared.u64 t, %1; cvt.u32.u64 %0, t; }"
        : "=r"(a) : "l"(p));
    return a;
}
__device__ __forceinline__ void cp16(uint32_t dst, const void* src, uint32_t bytes) {
    asm volatile("cp.async.cg.shared.global [%0], [%1], 16, %2;"
                 :: "r"(dst), "l"(src), "r"(bytes));
}
#define CP_COMMIT() asm volatile("cp.async.commit_group;" ::: "memory")
#define CP_WAIT(n)  asm volatile("cp.async.wait_group %0;" :: "n"(n) : "memory")

__device__ __forceinline__ void ldm_x4(uint32_t* r, uint32_t addr) {
    asm volatile("ldmatrix.sync.aligned.m8n8.x4.shared.b16 {%0,%1,%2,%3}, [%4];"
                 : "=r"(r[0]), "=r"(r[1]), "=r"(r[2]), "=r"(r[3]) : "r"(addr));
}
__device__ __forceinline__ void mma_f16(float* c, const uint32_t* a, const uint32_t* b) {
    asm volatile("mma.sync.aligned.m16n8k16.row.col.f32.f16.f16.f32 "
                 "{%0,%1,%2,%3}, {%4,%5,%6,%7}, {%8,%9}, {%0,%1,%2,%3};"
                 : "+f"(c[0]), "+f"(c[1]), "+f"(c[2]), "+f"(c[3])
                 : "r"(a[0]), "r"(a[1]), "r"(a[2]), "r"(a[3]), "r"(b[0]), "r"(b[1]));
}

// ---------------- merged prep: TE + x + W conversions AND degree count --------
__global__ void prep_kernel(const float4* __restrict__ user,
                            const float4* __restrict__ item,
                            const float4* __restrict__ x,
                            const float4* __restrict__ W0,
                            const float4* __restrict__ W1,
                            const float4* __restrict__ W2,
                            const float4* __restrict__ W3,
                            const int4* __restrict__ col4, int E4, int E,
                            const int* __restrict__ col,
                            int nu4, int total4) {
    __half2* te = reinterpret_cast<__half2*>(g_TE);
    __half2* xx = reinterpret_cast<__half2*>(g_X);
    __half2* ww = reinterpret_cast<__half2*>(g_W);
    const float4* Ws[4] = {W0, W1, W2, W3};
    const int tot_ax  = total4 * 2;
    const int tot_w   = tot_ax + 65536;
    const int tot_all = tot_w + E4;
    int gid = blockIdx.x * blockDim.x + threadIdx.x;
    for (int i = gid; i < tot_all; i += gridDim.x * blockDim.x) {
        if (i < total4) {
            float4 v = (i < nu4) ? user[i] : item[i - nu4];
            te[2 * i]     = __floats2half2_rn(v.x, v.y);
            te[2 * i + 1] = __floats2half2_rn(v.z, v.w);
        } else if (i < tot_ax) {
            int j = i - total4;
            float4 v = x[j];
            xx[2 * j]     = __floats2half2_rn(v.x, v.y);
            xx[2 * j + 1] = __floats2half2_rn(v.z, v.w);
        } else if (i < tot_w) {
            int j = i - tot_ax;
            float4 v = Ws[j >> 14][j & 16383];
            ww[2 * j]     = __floats2half2_rn(v.x, v.y);
            ww[2 * j + 1] = __floats2half2_rn(v.z, v.w);
        } else {
            int4 c = col4[i - tot_w];
            atomicAdd(&g_deg[c.x], 1);
            atomicAdd(&g_deg[c.y], 1);
            atomicAdd(&g_deg[c.z], 1);
            atomicAdd(&g_deg[c.w], 1);
        }
    }
    if (gid == 0)
        for (int e = E4 * 4; e < E; e++) atomicAdd(&g_deg[col[e]], 1);
}

// ---------------- single-pass decoupled-lookback scan -------------------------
__global__ void scan_kernel(int n, int E) {
    __shared__ int sh[1024];
    __shared__ int s_base;
    const int b = blockIdx.x;
    const int tid = threadIdx.x;
    const int i = b * 1024 + tid;
    int v = (i < n) ? g_deg[i] : 0;
    sh[tid] = v;
    __syncthreads();
    for (int off = 1; off < 1024; off <<= 1) {
        int t = (tid >= off) ? sh[tid - off] : 0;
        __syncthreads();
        sh[tid] += t;
        __syncthreads();
    }
    if (tid == 0) {
        unsigned long long total = (unsigned long long)(unsigned)sh[1023];
        atomicExch(&g_scanstate[b], (1ull << 32) | total);
        int base = 0;
        for (int j = b - 1; j >= 0;) {
            unsigned long long st;
            do { st = atomicAdd(&g_scanstate[j], 0ull); } while ((st >> 32) == 0ull);
            base += (int)(unsigned)st;
            if ((st >> 32) == 2ull) break;
            j--;
        }
        atomicExch(&g_scanstate[b], (2ull << 32) |
                   (unsigned long long)(unsigned)(base + sh[1023]));
        s_base = base;
    }
    __syncthreads();
    if (i < n) {
        int p = s_base + sh[tid] - v;
        g_ptr[i] = p;
        g_cur[i] = p;
    }
    if (i == 0) g_ptr[n] = E;
}

__global__ void scatter_kernel(const int4* __restrict__ row4,
                               const int4* __restrict__ col4, int E4, int E,
                               const int* __restrict__ row,
                               const int* __restrict__ col) {
    int i = blockIdx.x * blockDim.x + threadIdx.x;
    for (int e = i; e < E4; e += gridDim.x * blockDim.x) {
        int4 r = row4[e];
        int4 c = col4[e];
        g_src[atomicAdd(&g_cur[c.x], 1)] = r.x;
        g_src[atomicAdd(&g_cur[c.y], 1)] = r.y;
        g_src[atomicAdd(&g_cur[c.z], 1)] = r.z;
        g_src[atomicAdd(&g_cur[c.w], 1)] = r.w;
    }
    if (i == 0)
        for (int e = E4 * 4; e < E; e++)
            g_src[atomicAdd(&g_cur[col[e]], 1)] = row[e];
}

// ---------------- fp16 HMMA GEMM: paired-x4 B loads ----------------------------
#define S_A  0
#define S_W  16384
#define STG  32768
#define GEMM_SMEM (2 * STG)

__device__ __forceinline__ void gemm_core(
    const __half* __restrict__ A, const __half* __restrict__ W,
    const float* __restrict__ bias, const float* __restrict__ bias2,
    float* __restrict__ C, __half* __restrict__ Ch, int M,
    char* smem, uint32_t sb) {
    const int tid = threadIdx.x, wid = tid >> 5, lid = tid & 31;
    const int bm = blockIdx.x * 128;
    const int bn = blockIdx.y * 128;
    const int wm = (wid >> 2) * 64;
    const int wn = (wid & 3) * 32;

    float acc[4][4][4];
#pragma unroll
    for (int i = 0; i < 4; i++)
#pragma unroll
        for (int j = 0; j < 4; j++)
#pragma unroll
            for (int k = 0; k < 4; k++) acc[i][j][k] = 0.f;

    auto load_tile = [&](int kt, int stage) {
        const int koff = kt * 64;
        const uint32_t base = sb + stage * STG;
#pragma unroll
        for (int i = tid; i < 1024; i += 256) {
            int r = i >> 3, c = i & 7;
            int grow = bm + r;
            const char* g = (const char*)A + (size_t)grow * 512 + koff * 2 + c * 16;
            uint32_t d = base + S_A + r * 128 + ((c ^ (r & 7)) << 4);
            cp16(d, g, (grow < M) ? 16u : 0u);
        }
#pragma unroll
        for (int i = tid; i < 1024; i += 256) {
            int r = i >> 3, c = i & 7;
            const char* g = (const char*)W + (size_t)(bn + r) * 512 + koff * 2 + c * 16;
            uint32_t d = base + S_W + r * 128 + ((c ^ (r & 7)) << 4);
            cp16(d, g, 16u);
        }
        CP_COMMIT();
    };

    load_tile(0, 0);

#pragma unroll
    for (int t = 0; t < 4; t++) {
        const int st = t & 1;
        if (t + 1 < 4) {
            load_tile(t + 1, (t + 1) & 1);
            CP_WAIT(1);
        } else {
            CP_WAIT(0);
        }
        __syncthreads();

        const uint32_t base = sb + st * STG;
#pragma unroll
        for (int ks = 0; ks < 4; ks++) {
            uint32_t a[4][4], bb[8];
#pragma unroll
            for (int ma = 0; ma < 4; ma++) {
                int ar = wm + ma * 16 + (lid & 15);
                int ch = ks * 2 + (lid >> 4);
                ldm_x4(a[ma], base + S_A + ar * 128 + ((ch ^ (ar & 7)) << 4));
            }
            // paired B loads: one x4 covers two n8 fragments.
            // lanes 0-7:  na=2*na2,   k-lo | lanes 8-15:  na=2*na2,   k-hi
            // lanes 16-23: na=2*na2+1, k-lo | lanes 24-31: na=2*na2+1, k-hi
#pragma unroll
            for (int na2 = 0; na2 < 2; na2++) {
                int nr = wn + (na2 * 2 + (lid >> 4)) * 8 + (lid & 7);
                int ch = ks * 2 + ((lid >> 3) & 1);
                ldm_x4(bb + na2 * 4, base + S_W + nr * 128 + ((ch ^ (nr & 7)) << 4));
            }
#pragma unroll
            for (int ma = 0; ma < 4; ma++)
#pragma unroll
                for (int na = 0; na < 4; na++)
                    mma_f16(acc[ma][na], a[ma], bb + na * 2);
        }
        __syncthreads();
    }

    const int g = lid >> 2;
    const int tg = (lid & 3) * 2;
#pragma unroll
    for (int ma = 0; ma < 4; ma++) {
        int mr = bm + wm + ma * 16 + g;
#pragma unroll
        for (int na = 0; na < 4; na++) {
            int nc = bn + wn + na * 8 + tg;
            float b0 = bias[nc], b1 = bias[nc + 1];
            if (bias2) { b0 += bias2[nc]; b1 += bias2[nc + 1]; }
            float o00 = acc[ma][na][0] + b0, o01 = acc[ma][na][1] + b1;
            float o10 = acc[ma][na][2] + b0, o11 = acc[ma][na][3] + b1;
            if (Ch) {
                if (mr < M)
                    *(__half2*)(Ch + (size_t)mr * OUT_DIM + nc) = __floats2half2_rn(o00, o01);
                if (mr + 8 < M)
                    *(__half2*)(Ch + (size_t)(mr + 8) * OUT_DIM + nc) = __floats2half2_rn(o10, o11);
            } else {
                if (mr < M)
                    *(float2*)(C + (size_t)mr * OUT_DIM + nc) = make_float2(o00, o01);
                if (mr + 8 < M)
                    *(float2*)(C + (size_t)(mr + 8) * OUT_DIM + nc) = make_float2(o10, o11);
            }
        }
    }
}

// grid.z: 0 -> Q = TE@Wq, 1 -> K = TE@Wk + rel, 2 -> V = X@Wv
__global__ void __launch_bounds__(256, 2)
gemm_qkv_kernel(const float* __restrict__ rel,
                const float* __restrict__ bq, const float* __restrict__ bk,
                const float* __restrict__ bv, int M) {
    extern __shared__ char smem[];
    const uint32_t sb = smem_u32(smem);
    const int z = blockIdx.z;
    const __half* A  = (z == 2) ? g_X : g_TE;
    const __half* W  = g_W + (size_t)z * 65536;
    const float* bias  = (z == 0) ? bq : (z == 1) ? bk : bv;
    const float* bias2 = (z == 1) ? rel : nullptr;
    __half* Ch = (z == 0) ? g_Qh : (z == 1) ? g_Kh : g_Vh;
    gemm_core(A, W, bias, bias2, nullptr, Ch, M, smem, sb);
}

__global__ void __launch_bounds__(256, 2)
gemm_out_kernel(const float* __restrict__ bo, float* __restrict__ out, int M) {
    extern __shared__ char smem[];
    const uint32_t sb = smem_u32(smem);
    gemm_core(g_AG, g_W + 3 * 65536, bo, nullptr, out, nullptr, M, smem, sb);
}

// ---------------- per-node attention: 64 thr/node, separate K/V, 4-edge ILP ---
__global__ void __launch_bounds__(256)
attn_kernel(int N) {
    const int n = blockIdx.x * 4 + (threadIdx.x >> 6);
    if (n >= N) return;
    const int tid = threadIdx.x & 63;
    const int w = tid >> 5, lid = tid & 31;
    const int head = w * 4 + (lid >> 3);
    const int sub = lid & 7;
    const int qidx = head * 8 + sub;

    const int beg = g_ptr[n];
    const int end = g_ptr[n + 1];

    const uint2* Q2 = reinterpret_cast<const uint2*>(g_Qh);
    const uint2* K2 = reinterpret_cast<const uint2*>(g_Kh);
    const uint2* V2 = reinterpret_cast<const uint2*>(g_Vh);
    const int* __restrict__ src = g_src;

    uint2 qr = Q2[(size_t)n * 64 + qidx];
    float2 q01 = __half22float2(*(__half2*)&qr.x);
    float2 q23 = __half22float2(*(__half2*)&qr.y);
    const float inv_sqrt_dk = 0.17677669529663689f;

    float s = 0.f;
    float a0 = 0.f, a1 = 0.f, a2 = 0.f, a3 = 0.f;

    int i = beg;
    for (; i + 3 < end; i += 4) {
        int r0 = src[i], r1 = src[i + 1], r2 = src[i + 2], r3 = src[i + 3];
        uint2 k0 = K2[(size_t)r0 * 64 + qidx];
        uint2 k1 = K2[(size_t)r1 * 64 + qidx];
        uint2 k2 = K2[(size_t)r2 * 64 + qidx];
        uint2 k3 = K2[(size_t)r3 * 64 + qidx];
        uint2 v0 = V2[(size_t)r0 * 64 + qidx];
        uint2 v1 = V2[(size_t)r1 * 64 + qidx];
        uint2 v2 = V2[(size_t)r2 * 64 + qidx];
        uint2 v3 = V2[(size_t)r3 * 64 + qidx];

        float2 kA01 = __half22float2(*(__half2*)&k0.x), kA23 = __half22float2(*(__half2*)&k0.y);
        float2 kB01 = __half22float2(*(__half2*)&k1.x), kB23 = __half22float2(*(__half2*)&k1.y);
        float2 kC01 = __half22float2(*(__half2*)&k2.x), kC23 = __half22float2(*(__half2*)&k2.y);
        float2 kD01 = __half22float2(*(__half2*)&k3.x), kD23 = __half22float2(*(__half2*)&k3.y);

        float pA = q01.x * kA01.x + q01.y * kA01.y + q23.x * kA23.x + q23.y * kA23.y;
        float pB = q01.x * kB01.x + q01.y * kB01.y + q23.x * kB23.x + q23.y * kB23.y;
        float pC = q01.x * kC01.x + q01.y * kC01.y + q23.x * kC23.x + q23.y * kC23.y;
        float pD = q01.x * kD01.x + q01.y * kD01.y + q23.x * kD23.x + q23.y * kD23.y;

        pA += __shfl_xor_sync(0xffffffffu, pA, 4);
        pB += __shfl_xor_sync(0xffffffffu, pB, 4);
        pC += __shfl_xor_sync(0xffffffffu, pC, 4);
        pD += __shfl_xor_sync(0xffffffffu, pD, 4);
        pA += __shfl_xor_sync(0xffffffffu, pA, 2);
        pB += __shfl_xor_sync(0xffffffffu, pB, 2);
        pC += __shfl_xor_sync(0xffffffffu, pC, 2);
        pD += __shfl_xor_sync(0xffffffffu, pD, 2);
        pA += __shfl_xor_sync(0xffffffffu, pA, 1);
        pB += __shfl_xor_sync(0xffffffffu, pB, 1);
        pC += __shfl_xor_sync(0xffffffffu, pC, 1);
        pD += __shfl_xor_sync(0xffffffffu, pD, 1);

        float eA = __expf(pA * inv_sqrt_dk);
        float eB = __expf(pB * inv_sqrt_dk);
        float eC = __expf(pC * inv_sqrt_dk);
        float eD = __expf(pD * inv_sqrt_dk);
        s += (eA + eB) + (eC + eD);

        float2 vA01 = __half22float2(*(__half2*)&v0.x), vA23 = __half22float2(*(__half2*)&v0.y);
        float2 vB01 = __half22float2(*(__half2*)&v1.x), vB23 = __half22float2(*(__half2*)&v1.y);
        float2 vC01 = __half22float2(*(__half2*)&v2.x), vC23 = __half22float2(*(__half2*)&v2.y);
        float2 vD01 = __half22float2(*(__half2*)&v3.x), vD23 = __half22float2(*(__half2*)&v3.y);

        a0 += eA * vA01.x + eB * vB01.x + eC * vC01.x + eD * vD01.x;
        a1 += eA * vA01.y + eB * vB01.y + eC * vC01.y + eD * vD01.y;
        a2 += eA * vA23.x + eB * vB23.x + eC * vC23.x + eD * vD23.x;
        a3 += eA * vA23.y + eB * vB23.y + eC * vC23.y + eD * vD23.y;
    }
    for (; i < end; i++) {
        int r0 = src[i];
        uint2 k0 = K2[(size_t)r0 * 64 + qidx];
        uint2 v0 = V2[(size_t)r0 * 64 + qidx];
        float2 k01 = __half22float2(*(__half2*)&k0.x), k23 = __half22float2(*(__half2*)&k0.y);
        float p = q01.x * k01.x + q01.y * k01.y + q23.x * k23.x + q23.y * k23.y;
        p += __shfl_xor_sync(0xffffffffu, p, 4);
        p += __shfl_xor_sync(0xffffffffu, p, 2);
        p += __shfl_xor_sync(0xffffffffu, p, 1);
        float e = __expf(p * inv_sqrt_dk);
        s += e;
        float2 v01 = __half22float2(*(__half2*)&v0.x), v23 = __half22float2(*(__half2*)&v0.y);
        a0 += e * v01.x;
        a1 += e * v01.y;
        a2 += e * v23.x;
        a3 += e * v23.y;
    }

    float o0 = 0.f, o1 = 0.f, o2 = 0.f, o3 = 0.f;
    if (s > 0.f) {
        float inv = 1.f / s;
        o0 = a0 * inv; o1 = a1 * inv; o2 = a2 * inv; o3 = a3 * inv;
    }
    uint2 outv;
    *(__half2*)&outv.x = __floats2half2_rn(o0, o1);
    *(__half2*)&outv.y = __floats2half2_rn(o2, o3);
    reinterpret_cast<uint2*>(g_AG)[(size_t)n * 64 + qidx] = outv;
}

// ---------------- launch --------------------------------------------------------
extern "C" void kernel_launch(void* const* d_in, const int* in_sizes, int n_in,
                              void* d_out, int out_size) {
    const float* x    = (const float*)d_in[0];
    const int*   row  = (const int*)  d_in[1];
    const int*   col  = (const int*)  d_in[2];
    const float* rel  = (const float*)d_in[3];
    const float* user = (const float*)d_in[4];
    const float* item = (const float*)d_in[5];
    const float* Wq   = (const float*)d_in[6];
    const float* bq   = (const float*)d_in[7];
    const float* Wk   = (const float*)d_in[8];
    const float* bk   = (const float*)d_in[9];
    const float* Wv   = (const float*)d_in[10];
    const float* bv   = (const float*)d_in[11];
    const float* Wo   = (const float*)d_in[12];
    const float* bo   = (const float*)d_in[13];
    float* out = (float*)d_out;

    const int N  = in_sizes[0] / IN_DIM;
    const int E  = in_sizes[1];
    const int NU = in_sizes[4] / IN_DIM;
    const int E4 = E >> 2;

    int* dDeg;
    unsigned long long* dState;
    cudaGetSymbolAddress((void**)&dDeg, g_deg);
    cudaGetSymbolAddress((void**)&dState, g_scanstate);

    cudaFuncSetAttribute(gemm_qkv_kernel,
                         cudaFuncAttributeMaxDynamicSharedMemorySize, GEMM_SMEM);
    cudaFuncSetAttribute(gemm_out_kernel,
                         cudaFuncAttributeMaxDynamicSharedMemorySize, GEMM_SMEM);

    // 0. zero degree counters + scan state
    cudaMemsetAsync(dDeg, 0, (size_t)N * sizeof(int), 0);
    cudaMemsetAsync(dState, 0, 64 * sizeof(unsigned long long), 0);

    // 1. merged prep: fp16 conversions + degree count
    {
        int total4 = N * (IN_DIM / 4);
        int nu4 = NU * (IN_DIM / 4);
        prep_kernel<<<2560, 256>>>((const float4*)user, (const float4*)item,
                                   (const float4*)x,
                                   (const float4*)Wq, (const float4*)Wk,
                                   (const float4*)Wv, (const float4*)Wo,
                                   (const int4*)col, E4, E, col,
                                   nu4, total4);
    }

    // 2. CSR: single-pass scan + scatter
    int nb = (N + 1023) / 1024;
    scan_kernel<<<nb, 1024>>>(N, E);
    scatter_kernel<<<(E4 + 255) / 256, 256>>>((const int4*)row, (const int4*)col,
                                              E4, E, row, col);

    // 3. fused Q/K/V projections — ONE launch, grid.z = 3
    dim3 gg((N + 127) / 128, 2, 3);
    gemm_qkv_kernel<<<gg, 256, GEMM_SMEM>>>(rel, bq, bk, bv, N);

    // 4. attention
    attn_kernel<<<(N + 3) / 4, 256>>>(N);

    // 5. output projection -> fp32 out
    dim3 go((N + 127) / 128, 2);
    gemm_out_kernel<<<go, 256, GEMM_SMEM>>>(bo, out, N);
}